// round 12
// baseline (speedup 1.0000x reference)
#include <cuda_runtime.h>
#include <cuda_fp16.h>
#include <cstdint>

// Problem constants
#define Bn   16
#define Tn   512
#define Fn   32
#define CIn  128
#define COn  128
#define Kn   3
#define DILn 2

#define NTHREADS 512           // 16 warps: 4(M) x 4(N), warp tile 64x32
#define GRIDX    148           // persistent CTAs (one wave)
#define NTILES   1024          // 32 f * 16 b * 2 t-segments (M=256)

// B resident: 3 taps x 4 ci-planes x 128 rows x 64B = 96KB
#define B_PLANE_BYTES 8192
#define B_TAP_BYTES   (4 * B_PLANE_BYTES)     // 32768
#define B_TOTAL       (3 * B_TAP_BYTES)       // 98304
// A buffer: 260 rows x 256B (full 128 ci per row, fp16), double buffered
#define A_ROW_BYTES   256
#define A_ROWS        260
#define A_BUF_BYTES   (A_ROWS * A_ROW_BYTES)  // 66560 (512-aligned)
#define DYN_SMEM (B_TOTAL + 2 * A_BUF_BYTES)  // 231424 (226KB)

#define A_F4   (A_ROWS * 32)   // float4s per A tile = 8320

// A swizzle: XOR 16B-granule index (bits 4-6) with row (bits 8-10)
#define SWZA(off) ((off) ^ ((((off) >> 8) & 7) << 4))
// B swizzle (64B rows)
#define SWZ64(off) ((off) ^ (((off) >> 3) & 0x30))

// Weights as fp16: wBh[f][tap][o][ci]
__device__ __half g_wBh[Fn * Kn * COn * CIn];

// ---------------------------------------------------------------------------
__global__ void prep_w(const float* __restrict__ w) {
    int idx = blockIdx.x * blockDim.x + threadIdx.x;
    const int total = Fn * Kn * COn * CIn;
    if (idx >= total) return;
    int i = idx % CIn;
    int o = (idx / CIn) % COn;
    int k = (idx / (CIn * COn)) % Kn;
    int f = idx / (CIn * COn * Kn);
    g_wBh[idx] = __float2half_rn(w[((f * COn + o) * CIn + i) * Kn + k]);
}

// ---------------------------------------------------------------------------
__device__ __forceinline__ uint32_t smem_u32(const void* p) {
    uint32_t a;
    asm("{ .reg .u64 t; cvta.to.shared.u64 t, %1; cvt.u32.u64 %0, t; }" : "=r"(a) : "l"(p));
    return a;
}
__device__ __forceinline__ void cp16(uint32_t saddr, const void* gaddr) {
    asm volatile("cp.async.cg.shared.global [%0], [%1], 16;"
                 :: "r"(saddr), "l"(gaddr));
}
__device__ __forceinline__ void sts64(uint32_t saddr, uint32_t v0, uint32_t v1) {
    asm volatile("st.shared.v2.b32 [%0], {%1, %2};" :: "r"(saddr), "r"(v0), "r"(v1));
}
__device__ __forceinline__ void ldsm_x4(uint32_t& r0, uint32_t& r1, uint32_t& r2, uint32_t& r3,
                                        uint32_t addr) {
    asm volatile("ldmatrix.sync.aligned.m8n8.x4.shared.b16 {%0,%1,%2,%3}, [%4];"
                 : "=r"(r0), "=r"(r1), "=r"(r2), "=r"(r3) : "r"(addr));
}
__device__ __forceinline__ void mma_f16(float* c, const uint32_t* a, const uint32_t* b) {
    asm volatile(
        "mma.sync.aligned.m16n8k16.row.col.f32.f16.f16.f32 "
        "{%0,%1,%2,%3}, {%4,%5,%6,%7}, {%8,%9}, {%0,%1,%2,%3};"
        : "+f"(c[0]), "+f"(c[1]), "+f"(c[2]), "+f"(c[3])
        : "r"(a[0]), "r"(a[1]), "r"(a[2]), "r"(a[3]), "r"(b[0]), "r"(b[1]));
}

// ---------------------------------------------------------------------------
// Persistent kernel. Tile = 256 t-rows x 128 CO, f-major order.
// B: 3 taps resident (96KB), reloaded at most once per CTA.
// A: double-buffered fp16 (256B rows); next tile's A loaded (LDG->cvt->STS)
// between tap1 and tap2, hidden by other warps' compute. One barrier/tile.
// ---------------------------------------------------------------------------
__global__ __launch_bounds__(NTHREADS, 1)
void conv_mma_kernel(const float* __restrict__ x,
                     const float* __restrict__ bias,
                     float* __restrict__ y) {
    extern __shared__ char dsm[];

    const int kcta = blockIdx.x;
    const int tid = threadIdx.x;
    const int wid = tid >> 5;
    const int lane = tid & 31;
    const int wm = (wid & 3) * 64;       // warp M base (0,64,128,192)
    const int wn = (wid >> 2) * 32;      // warp N base (0,32,64,96)

    const int start = (kcta * NTILES) / GRIDX;
    const int end   = ((kcta + 1) * NTILES) / GRIDX;

    const uint32_t smb = smem_u32(dsm);
    const uint32_t Bbase = smb;
    const uint32_t Abuf[2] = { smb + B_TOTAL, smb + B_TOTAL + A_BUF_BYTES };

    // ---- B loader (one f): 6144 float4s, 12 per thread ----
    auto issue_B = [&](int f_) {
        const __half* wf = g_wBh + (long long)f_ * Kn * COn * CIn;
        #pragma unroll
        for (int j = 0; j < 12; j++) {
            const int lin   = j * NTHREADS + tid;
            const int tap   = lin / 2048;
            const int rem1  = lin % 2048;
            const int plane = rem1 >> 9;
            const int rem   = rem1 & 511;
            const int row   = rem >> 2;
            const int c16   = rem & 3;
            cp16(Bbase + tap * B_TAP_BYTES + plane * B_PLANE_BYTES
                       + SWZ64(row * 64 + c16 * 16),
                 wf + (long long)tap * (COn * CIn) + (long long)row * CIn
                    + plane * 32 + c16 * 8);
        }
        asm volatile("cp.async.commit_group;");
    };

    // ---- A loader: LDG fp32 -> cvt fp16 -> STS (swizzled 256B rows) ----
    auto loadA = [&](int f_, int b_, int t0_, uint32_t Ab_) {
        const float* xb = x + ((long long)b_ * Tn * Fn + f_) * CIn;
        #pragma unroll 4
        for (int i = 0; i < 17; i++) {
            const int idx2 = tid + i * NTHREADS;
            if (idx2 < A_F4) {
                const int row = idx2 >> 5;
                const int q   = idx2 & 31;
                const int tg  = t0_ - 4 + row;
                float4 v = make_float4(0.f, 0.f, 0.f, 0.f);
                if (tg >= 0)
                    v = *reinterpret_cast<const float4*>(
                        xb + (long long)tg * (Fn * CIn) + q * 4);
                __half2 h0 = __floats2half2_rn(v.x, v.y);
                __half2 h1 = __floats2half2_rn(v.z, v.w);
                sts64(Ab_ + SWZA(row * 256 + q * 8),
                      *reinterpret_cast<uint32_t*>(&h0),
                      *reinterpret_cast<uint32_t*>(&h1));
            }
        }
    };

    // tile decode: idx = f*32 + b*2 + seg
    auto dec_f  = [](int idx) { return idx >> 5; };
    auto dec_b  = [](int idx) { return (idx >> 1) & 15; };
    auto dec_t0 = [](int idx) { return (idx & 1) * 256; };

    // ---- prologue ----
    int curf = dec_f(start);
    issue_B(curf);
    loadA(curf, dec_b(start), dec_t0(start), Abuf[0]);
    asm volatile("cp.async.wait_group 0;");
    __syncthreads();

    // ldmatrix lane addressing
    const int a_row = wm + (lane & 15);
    const int a_cb  = (lane >> 4) * 16;                  // 16B granule within kstep
    const int b_row = wn + (lane & 7) + ((lane >> 4) << 3);
    const int b_cb  = ((lane >> 3) & 1) * 16;

    int p = 0;   // current A buffer

    float acc[4][4][4];                  // [mf 16-row][nfo 8-col][elem]

    auto compute_tap = [&](int tap, uint32_t Ab_) {
        const uint32_t Bt = Bbase + tap * B_TAP_BYTES;
        const int arow_sh = 2 * tap;
        #pragma unroll
        for (int plane = 0; plane < 4; plane++) {
            const uint32_t Bb = Bt + plane * B_PLANE_BYTES;
            #pragma unroll
            for (int ks = 0; ks < 2; ks++) {
                uint32_t afr[4][4], bfr[4][2];
                #pragma unroll
                for (int mf = 0; mf < 4; mf++)
                    ldsm_x4(afr[mf][0], afr[mf][1], afr[mf][2], afr[mf][3],
                            Ab_ + SWZA((a_row + mf * 16 + arow_sh) * 256
                                       + plane * 64 + ks * 32 + a_cb));
                #pragma unroll
                for (int nf2 = 0; nf2 < 2; nf2++) {
                    uint32_t r0, r1, r2, r3;
                    ldsm_x4(r0, r1, r2, r3,
                            Bb + SWZ64((b_row + nf2 * 16) * 64 + ks * 32 + b_cb));
                    bfr[nf2 * 2][0] = r0;     bfr[nf2 * 2][1] = r1;
                    bfr[nf2 * 2 + 1][0] = r2; bfr[nf2 * 2 + 1][1] = r3;
                }
                #pragma unroll
                for (int mf = 0; mf < 4; mf++)
                    #pragma unroll
                    for (int nfo = 0; nfo < 4; nfo++)
                        mma_f16(acc[mf][nfo], afr[mf], bfr[nfo]);
            }
        }
    };

    // ---- persistent tile loop ----
    for (int idx = start; idx < end; idx++) {
        const int f  = dec_f(idx);
        const int b  = dec_b(idx);
        const int t0 = dec_t0(idx);
        const bool have_next = (idx + 1 < end);

        // bias + acc init
        #pragma unroll
        for (int nfo = 0; nfo < 4; nfo++) {
            const int n = wn + nfo * 8 + (lane & 3) * 2;
            const float b0 = __ldg(bias + f * COn + n);
            const float b1 = __ldg(bias + f * COn + n + 1);
            #pragma unroll
            for (int mf = 0; mf < 4; mf++) {
                acc[mf][nfo][0] = b0; acc[mf][nfo][1] = b1;
                acc[mf][nfo][2] = b0; acc[mf][nfo][3] = b1;
            }
        }

        compute_tap(0, Abuf[p]);
        compute_tap(1, Abuf[p]);

        // load next tile's A into the other buffer (hidden by other warps)
        int nf = curf;
        if (have_next) {
            nf = dec_f(idx + 1);
            loadA(nf, dec_b(idx + 1), dec_t0(idx + 1), Abuf[p ^ 1]);
        }

        compute_tap(2, Abuf[p]);

        // store y
        #pragma unroll
        for (int mf = 0; mf < 4; mf++) {
            #pragma unroll
            for (int r2 = 0; r2 < 2; r2++) {
                const int t = t0 + wm + mf * 16 + (lane >> 2) + r2 * 8;
                float* yrow = y + ((long long)(b * Tn + t) * Fn + f) * COn;
                #pragma unroll
                for (int nfo = 0; nfo < 4; nfo++) {
                    const int n = wn + nfo * 8 + (lane & 3) * 2;
                    *reinterpret_cast<float2*>(yrow + n) =
                        make_float2(acc[mf][nfo][r2 * 2], acc[mf][nfo][r2 * 2 + 1]);
                }
            }
        }

        if (have_next && nf != curf) {
            // B reload: all warps must be done reading old B first
            __syncthreads();
            issue_B(nf);
            curf = nf;
            asm volatile("cp.async.wait_group 0;");
        }
        __syncthreads();     // the one steady-state barrier
        p ^= 1;
    }
}

// ---------------------------------------------------------------------------
extern "C" void kernel_launch(void* const* d_in, const int* in_sizes, int n_in,
                              void* d_out, int out_size) {
    const float* x    = (const float*)d_in[0];  // [B, T, F, CI]
    const float* w    = (const float*)d_in[1];  // [F, CO, CI, K]
    const float* bias = (const float*)d_in[2];  // [F, CO]
    float* y = (float*)d_out;                   // [B, T, F, CO]
    (void)in_sizes; (void)n_in; (void)out_size;

    {
        const int total = Fn * Kn * COn * CIn;
        prep_w<<<(total + 255) / 256, 256>>>(w);
    }
    {
        static bool attr_set = false;
        if (!attr_set) {
            cudaFuncSetAttribute(conv_mma_kernel,
                                 cudaFuncAttributeMaxDynamicSharedMemorySize, DYN_SMEM);
            attr_set = true;
        }
        conv_mma_kernel<<<GRIDX, NTHREADS, DYN_SMEM>>>(x, bias, y);
    }
}

// round 13
// speedup vs baseline: 1.1407x; 1.1407x over previous
#include <cuda_runtime.h>
#include <cuda_fp16.h>
#include <cstdint>

// Problem constants
#define Bn   16
#define Tn   512
#define Fn   32
#define CIn  128
#define COn  128
#define Kn   3
#define DILn 2

#define NTHREADS 512           // 16 warps: 4(M) x 4(N), warp tile 64x32
#define GRIDX    148           // persistent CTAs (one wave)
#define NTILES   1024          // 32 f * 16 b * 2 t-segments (M=256)

// B resident: 3 taps x 4 ci-planes x 128 rows x 64B = 96KB
#define B_PLANE_BYTES 8192
#define B_TAP_BYTES   (4 * B_PLANE_BYTES)     // 32768
#define B_TOTAL       (3 * B_TAP_BYTES)       // 98304
// A buffer: 260 rows x 256B (full 128 ci per row, fp16), double buffered
#define A_ROW_BYTES   256
#define A_ROWS        260
#define A_BUF_BYTES   (A_ROWS * A_ROW_BYTES)  // 66560
#define DYN_SMEM (B_TOTAL + 2 * A_BUF_BYTES)  // 231424 (226KB)

#define A_F4   (A_ROWS * 32)   // float4s per A tile = 8320

// A swizzle: XOR 16B-granule bits (4-6) with row bits (8-10)
#define SWZA(off) ((off) ^ ((((off) >> 8) & 7) << 4))
// B swizzle (64B rows)
#define SWZ64(off) ((off) ^ (((off) >> 3) & 0x30))

// Weights as fp16: wBh[f][tap][o][ci]
__device__ __half g_wBh[Fn * Kn * COn * CIn];

// ---------------------------------------------------------------------------
__global__ void prep_w(const float* __restrict__ w) {
    int idx = blockIdx.x * blockDim.x + threadIdx.x;
    const int total = Fn * Kn * COn * CIn;
    if (idx >= total) return;
    int i = idx % CIn;
    int o = (idx / CIn) % COn;
    int k = (idx / (CIn * COn)) % Kn;
    int f = idx / (CIn * COn * Kn);
    g_wBh[idx] = __float2half_rn(w[((f * COn + o) * CIn + i) * Kn + k]);
}

// ---------------------------------------------------------------------------
__device__ __forceinline__ uint32_t smem_u32(const void* p) {
    uint32_t a;
    asm("{ .reg .u64 t; cvta.to.shared.u64 t, %1; cvt.u32.u64 %0, t; }" : "=r"(a) : "l"(p));
    return a;
}
__device__ __forceinline__ void cp16(uint32_t saddr, const void* gaddr) {
    asm volatile("cp.async.cg.shared.global [%0], [%1], 16;"
                 :: "r"(saddr), "l"(gaddr));
}
__device__ __forceinline__ void sts64(uint32_t saddr, uint32_t v0, uint32_t v1) {
    asm volatile("st.shared.v2.b32 [%0], {%1, %2};" :: "r"(saddr), "r"(v0), "r"(v1));
}
__device__ __forceinline__ void ldsm_x4(uint32_t& r0, uint32_t& r1, uint32_t& r2, uint32_t& r3,
                                        uint32_t addr) {
    asm volatile("ldmatrix.sync.aligned.m8n8.x4.shared.b16 {%0,%1,%2,%3}, [%4];"
                 : "=r"(r0), "=r"(r1), "=r"(r2), "=r"(r3) : "r"(addr));
}
__device__ __forceinline__ void mma_f16(float* c, const uint32_t* a, const uint32_t* b) {
    asm volatile(
        "mma.sync.aligned.m16n8k16.row.col.f32.f16.f16.f32 "
        "{%0,%1,%2,%3}, {%4,%5,%6,%7}, {%8,%9}, {%0,%1,%2,%3};"
        : "+f"(c[0]), "+f"(c[1]), "+f"(c[2]), "+f"(c[3])
        : "r"(a[0]), "r"(a[1]), "r"(a[2]), "r"(a[3]), "r"(b[0]), "r"(b[1]));
}

// ---------------------------------------------------------------------------
// Persistent kernel. Tile = 256 t-rows x 128 CO, f-major order.
// B: 3 taps resident (96KB), reloaded at most once per CTA.
// A: double-buffered fp16 (256B rows). Next tile's A is prefetched in THREE
// register chunks (<=6 float4 live), each chunk's LDG hidden under a full
// tap of compute; STS interleaved at tap boundaries. One barrier per tile.
// ---------------------------------------------------------------------------
__global__ __launch_bounds__(NTHREADS, 1)
void conv_mma_kernel(const float* __restrict__ x,
                     const float* __restrict__ bias,
                     float* __restrict__ y) {
    extern __shared__ char dsm[];

    const int kcta = blockIdx.x;
    const int tid = threadIdx.x;
    const int wid = tid >> 5;
    const int lane = tid & 31;
    const int wm = (wid & 3) * 64;       // warp M base (0,64,128,192)
    const int wn = (wid >> 2) * 32;      // warp N base (0,32,64,96)

    const int start = (kcta * NTILES) / GRIDX;
    const int end   = ((kcta + 1) * NTILES) / GRIDX;

    const uint32_t smb = smem_u32(dsm);
    const uint32_t Bbase = smb;
    const uint32_t Abuf[2] = { smb + B_TOTAL, smb + B_TOTAL + A_BUF_BYTES };

    // ---- B loader (one f): 6144 float4s, 12 per thread ----
    auto issue_B = [&](int f_) {
        const __half* wf = g_wBh + (long long)f_ * Kn * COn * CIn;
        #pragma unroll
        for (int j = 0; j < 12; j++) {
            const int lin   = j * NTHREADS + tid;
            const int tap   = lin / 2048;
            const int rem1  = lin % 2048;
            const int plane = rem1 >> 9;
            const int rem   = rem1 & 511;
            const int row   = rem >> 2;
            const int c16   = rem & 3;
            cp16(Bbase + tap * B_TAP_BYTES + plane * B_PLANE_BYTES
                       + SWZ64(row * 64 + c16 * 16),
                 wf + (long long)tap * (COn * CIn) + (long long)row * CIn
                    + plane * 32 + c16 * 8);
        }
        asm volatile("cp.async.commit_group;");
    };

    // ---- A chunk prefetch: global -> regs (n <= 6 float4s) ----
    auto ldg_chunk = [&](int f_, int b_, int t0_, int c0, int n, float4* v) {
        const float* xb = x + ((long long)b_ * Tn * Fn + f_) * CIn;
        #pragma unroll
        for (int i = 0; i < 6; i++) {
            if (i < n) {
                const int idx2 = tid + (c0 + i) * NTHREADS;
                const int row = idx2 >> 5;
                const int q   = idx2 & 31;
                const int tg  = t0_ - 4 + row;
                v[i] = make_float4(0.f, 0.f, 0.f, 0.f);
                if (idx2 < A_F4 && tg >= 0)
                    v[i] = *reinterpret_cast<const float4*>(
                        xb + (long long)tg * (Fn * CIn) + q * 4);
            }
        }
    };
    // ---- A chunk commit: regs -> smem fp16 (swizzled 256B rows) ----
    auto sts_chunk = [&](const float4* v, int c0, int n, uint32_t Ab_) {
        #pragma unroll
        for (int i = 0; i < 6; i++) {
            if (i < n) {
                const int idx2 = tid + (c0 + i) * NTHREADS;
                if (idx2 < A_F4) {
                    const int row = idx2 >> 5;
                    const int q   = idx2 & 31;
                    __half2 h0 = __floats2half2_rn(v[i].x, v[i].y);
                    __half2 h1 = __floats2half2_rn(v[i].z, v[i].w);
                    sts64(Ab_ + SWZA(row * 256 + q * 8),
                          *reinterpret_cast<const uint32_t*>(&h0),
                          *reinterpret_cast<const uint32_t*>(&h1));
                }
            }
        }
    };

    // tile decode: idx = f*32 + b*2 + seg
    auto dec_f  = [](int idx) { return idx >> 5; };
    auto dec_b  = [](int idx) { return (idx >> 1) & 15; };
    auto dec_t0 = [](int idx) { return (idx & 1) * 256; };

    // ---- prologue ----
    int curf = dec_f(start);
    issue_B(curf);
    {
        float4 v[6];
        const int b0_ = dec_b(start), t00 = dec_t0(start);
        ldg_chunk(curf, b0_, t00, 0, 6, v);  sts_chunk(v, 0, 6, Abuf[0]);
        ldg_chunk(curf, b0_, t00, 6, 6, v);  sts_chunk(v, 6, 6, Abuf[0]);
        ldg_chunk(curf, b0_, t00, 12, 5, v); sts_chunk(v, 12, 5, Abuf[0]);
    }
    asm volatile("cp.async.wait_group 0;");
    __syncthreads();

    // ldmatrix lane addressing
    const int a_row = wm + (lane & 15);
    const int a_cb  = (lane >> 4) * 16;
    const int b_row = wn + (lane & 7) + ((lane >> 4) << 3);
    const int b_cb  = ((lane >> 3) & 1) * 16;

    int p = 0;   // current A buffer

    float acc[4][4][4];                  // [mf 16-row][nfo 8-col][elem]

    auto compute_tap = [&](int tap, uint32_t Ab_) {
        const uint32_t Bt = Bbase + tap * B_TAP_BYTES;
        const int arow_sh = 2 * tap;
        #pragma unroll
        for (int plane = 0; plane < 4; plane++) {
            const uint32_t Bb = Bt + plane * B_PLANE_BYTES;
            #pragma unroll
            for (int ks = 0; ks < 2; ks++) {
                uint32_t afr[4][4], bfr[4][2];
                #pragma unroll
                for (int mf = 0; mf < 4; mf++)
                    ldsm_x4(afr[mf][0], afr[mf][1], afr[mf][2], afr[mf][3],
                            Ab_ + SWZA((a_row + mf * 16 + arow_sh) * 256
                                       + plane * 64 + ks * 32 + a_cb));
                #pragma unroll
                for (int nf2 = 0; nf2 < 2; nf2++) {
                    uint32_t r0, r1, r2, r3;
                    ldsm_x4(r0, r1, r2, r3,
                            Bb + SWZ64((b_row + nf2 * 16) * 64 + ks * 32 + b_cb));
                    bfr[nf2 * 2][0] = r0;     bfr[nf2 * 2][1] = r1;
                    bfr[nf2 * 2 + 1][0] = r2; bfr[nf2 * 2 + 1][1] = r3;
                }
                #pragma unroll
                for (int mf = 0; mf < 4; mf++)
                    #pragma unroll
                    for (int nfo = 0; nfo < 4; nfo++)
                        mma_f16(acc[mf][nfo], afr[mf], bfr[nfo]);
            }
        }
    };

    // ---- persistent tile loop ----
    for (int idx = start; idx < end; idx++) {
        const int f  = dec_f(idx);
        const int b  = dec_b(idx);
        const int t0 = dec_t0(idx);
        const bool have_next = (idx + 1 < end);
        int nf = curf, nb = 0, nt0 = 0;
        if (have_next) { nf = dec_f(idx + 1); nb = dec_b(idx + 1); nt0 = dec_t0(idx + 1); }

        // bias + acc init
        #pragma unroll
        for (int nfo = 0; nfo < 4; nfo++) {
            const int n = wn + nfo * 8 + (lane & 3) * 2;
            const float b0 = __ldg(bias + f * COn + n);
            const float b1 = __ldg(bias + f * COn + n + 1);
            #pragma unroll
            for (int mf = 0; mf < 4; mf++) {
                acc[mf][nfo][0] = b0; acc[mf][nfo][1] = b1;
                acc[mf][nfo][2] = b0; acc[mf][nfo][3] = b1;
            }
        }

        float4 v[6];
        const uint32_t An = Abuf[p ^ 1];

        compute_tap(0, Abuf[p]);
        if (have_next) ldg_chunk(nf, nb, nt0, 0, 6, v);       // hidden under tap1

        compute_tap(1, Abuf[p]);
        if (have_next) { sts_chunk(v, 0, 6, An); ldg_chunk(nf, nb, nt0, 6, 6, v); }

        compute_tap(2, Abuf[p]);
        if (have_next) { sts_chunk(v, 6, 6, An); ldg_chunk(nf, nb, nt0, 12, 5, v); }

        // store y
        #pragma unroll
        for (int mf = 0; mf < 4; mf++) {
            #pragma unroll
            for (int r2 = 0; r2 < 2; r2++) {
                const int t = t0 + wm + mf * 16 + (lane >> 2) + r2 * 8;
                float* yrow = y + ((long long)(b * Tn + t) * Fn + f) * COn;
                #pragma unroll
                for (int nfo = 0; nfo < 4; nfo++) {
                    const int n = wn + nfo * 8 + (lane & 3) * 2;
                    *reinterpret_cast<float2*>(yrow + n) =
                        make_float2(acc[mf][nfo][r2 * 2], acc[mf][nfo][r2 * 2 + 1]);
                }
            }
        }

        if (have_next) sts_chunk(v, 12, 5, An);

        if (have_next && nf != curf) {
            // B reload: all warps must be done reading old B first
            __syncthreads();
            issue_B(nf);
            curf = nf;
            asm volatile("cp.async.wait_group 0;");
        }
        __syncthreads();     // the one steady-state barrier
        p ^= 1;
    }
}

// ---------------------------------------------------------------------------
extern "C" void kernel_launch(void* const* d_in, const int* in_sizes, int n_in,
                              void* d_out, int out_size) {
    const float* x    = (const float*)d_in[0];  // [B, T, F, CI]
    const float* w    = (const float*)d_in[1];  // [F, CO, CI, K]
    const float* bias = (const float*)d_in[2];  // [F, CO]
    float* y = (float*)d_out;                   // [B, T, F, CO]
    (void)in_sizes; (void)n_in; (void)out_size;

    {
        const int total = Fn * Kn * COn * CIn;
        prep_w<<<(total + 255) / 256, 256>>>(w);
    }
    {
        static bool attr_set = false;
        if (!attr_set) {
            cudaFuncSetAttribute(conv_mma_kernel,
                                 cudaFuncAttributeMaxDynamicSharedMemorySize, DYN_SMEM);
            attr_set = true;
        }
        conv_mma_kernel<<<GRIDX, NTHREADS, DYN_SMEM>>>(x, bias, y);
    }
}